// round 10
// baseline (speedup 1.0000x reference)
#include <cuda_runtime.h>
#include <cuda_fp16.h>
#include <cstdint>

#define M_TOTAL 16384
#define N_TOTAL 4096
#define K_TOTAL 4096
#define RANK    8

#define BM 128
#define BN 256
#define BK 32
#define NITER   (K_TOTAL / BK)     // 128
#define THREADS 512
#define STAGES  8
#define N_TILES (N_TOTAL / BN)     // 16
#define M_TILES (M_TOTAL / BM)     // 128

#define SM_STAGE 24576             // A 8KB + B 16KB (fp16)
#define SM_AUX   (STAGES * SM_STAGE)              // 196608
#define SMEM_TOTAL (SM_AUX + 4096 + 8192 + 1024)  // 209920

static __device__ float  g_hc[M_TOTAL * RANK];
static __device__ __half g_xh[(size_t)M_TOTAL * K_TOTAL];   // 128 MB
static __device__ __half g_wh[(size_t)N_TOTAL * K_TOTAL];   // 32 MB

// ---------------- helpers ----------------
__device__ __forceinline__ uint32_t smem_u32(const void* p) {
    uint32_t a;
    asm("{ .reg .u64 t; cvta.to.shared.u64 t, %1; cvt.u32.u64 %0, t; }" : "=r"(a) : "l"(p));
    return a;
}
__device__ __forceinline__ void cp_async16(uint32_t dst, const void* src) {
    asm volatile("cp.async.cg.shared.global [%0], [%1], 16;" :: "r"(dst), "l"(src) : "memory");
}
__device__ __forceinline__ void cp_commit() {
    asm volatile("cp.async.commit_group;" ::: "memory");
}
template <int N>
__device__ __forceinline__ void cp_wait() {
    asm volatile("cp.async.wait_group %0;" :: "n"(N) : "memory");
}
__device__ __forceinline__ void ldsm4(uint32_t* r, uint32_t a) {
    asm volatile("ldmatrix.sync.aligned.m8n8.x4.shared.b16 {%0,%1,%2,%3}, [%4];"
                 : "=r"(r[0]), "=r"(r[1]), "=r"(r[2]), "=r"(r[3]) : "r"(a));
}
__device__ __forceinline__ void mma_f16(float* d, const uint32_t* a, const uint32_t* b) {
    asm volatile("mma.sync.aligned.m16n8k16.row.col.f32.f16.f16.f32 "
                 "{%0,%1,%2,%3}, {%4,%5,%6,%7}, {%8,%9}, {%0,%1,%2,%3};"
                 : "+f"(d[0]), "+f"(d[1]), "+f"(d[2]), "+f"(d[3])
                 : "r"(a[0]), "r"(a[1]), "r"(a[2]), "r"(a[3]), "r"(b[0]), "r"(b[1]));
}
// row-major fp16 tile, 32 halves (64B = 4x16B chunks) per row, XOR swizzle
__device__ __forceinline__ uint32_t swz(int row, int kc) {
    return (uint32_t)(row * 64 + ((kc ^ ((row >> 1) & 3)) << 4));
}

// ---------------- fused prep: convw (all blocks) + hc/convx (blocks<128) ----
__global__ void __launch_bounds__(1024) prep_kernel(
    const float* __restrict__ x, const float* __restrict__ codes,
    const float* __restrict__ V, const float* __restrict__ W)
{
    extern __shared__ float sVT[];   // [8][4096] = 128 KB
    int tid = threadIdx.x;

    // phase 1: W -> fp16, grid-stride over all blocks
    {
        size_t total = (size_t)N_TOTAL * K_TOTAL;
        size_t stride = (size_t)gridDim.x * 1024 * 4;
        for (size_t i = ((size_t)blockIdx.x * 1024 + tid) * 4; i < total; i += stride) {
            float4 v = *reinterpret_cast<const float4*>(&W[i]);
            __half2* dst = reinterpret_cast<__half2*>(&g_wh[i]);
            dst[0] = __floats2half2_rn(v.x, v.y);
            dst[1] = __floats2half2_rn(v.z, v.w);
        }
    }
    if (blockIdx.x >= 128) return;

    // phase 2: hc[m,r] = 2*codes[m,r]*sum_d x[m,d]*V[d,r]  +  x -> fp16
    for (int idx = tid; idx < K_TOTAL * RANK; idx += 1024) {
        int d = idx >> 3, r = idx & 7;
        sVT[r * K_TOTAL + d] = V[idx];
    }
    __syncthreads();

    int wid = tid >> 5, lane = tid & 31;
    int m0 = blockIdx.x * 128 + wid * 4;

    float acc[4][8];
#pragma unroll
    for (int a = 0; a < 4; ++a)
#pragma unroll
        for (int r = 0; r < 8; ++r) acc[a][r] = 0.f;

    for (int it = 0; it < 32; ++it) {
        int d = it * 128 + lane * 4;
        float4 xr[4];
#pragma unroll
        for (int a = 0; a < 4; ++a) {
            xr[a] = *reinterpret_cast<const float4*>(&x[(size_t)(m0 + a) * K_TOTAL + d]);
            __half2* dst = reinterpret_cast<__half2*>(&g_xh[(size_t)(m0 + a) * K_TOTAL + d]);
            dst[0] = __floats2half2_rn(xr[a].x, xr[a].y);
            dst[1] = __floats2half2_rn(xr[a].z, xr[a].w);
        }
#pragma unroll
        for (int r = 0; r < 8; ++r) {
            float4 v = *reinterpret_cast<const float4*>(&sVT[r * K_TOTAL + d]);
#pragma unroll
            for (int a = 0; a < 4; ++a)
                acc[a][r] += xr[a].x * v.x + xr[a].y * v.y + xr[a].z * v.z + xr[a].w * v.w;
        }
    }
#pragma unroll
    for (int o = 16; o > 0; o >>= 1)
#pragma unroll
        for (int a = 0; a < 4; ++a)
#pragma unroll
            for (int r = 0; r < 8; ++r)
                acc[a][r] += __shfl_xor_sync(0xffffffffu, acc[a][r], o);

    if (lane == 0) {
#pragma unroll
        for (int a = 0; a < 4; ++a)
#pragma unroll
            for (int r = 0; r < 8; ++r)
                g_hc[(size_t)(m0 + a) * RANK + r] =
                    2.0f * codes[(size_t)(m0 + a) * RANK + r] * acc[a][r];
    }
}

// -- main GEMM: fp16 m16n8k16, CTA 128x256, 512 thr, warp 32x64,
//    8-stage ring, lookahead 4, ONE barrier per 4 K-chunks.
//    Quad i consumes stages {i..i+3}%8 and loads into {i+4..i+7}%8 (disjoint). --
__global__ void __launch_bounds__(THREADS, 1) gemm_kernel(
    const float* __restrict__ bias, const float* __restrict__ U,
    float* __restrict__ out)
{
    extern __shared__ char smem[];
    uint32_t sb = smem_u32(smem);
    int tid = threadIdx.x, lane = tid & 31, wid = tid >> 5;
    int wm = wid & 3, wn = wid >> 2;        // warp grid 4(M) x 4(N), tile 32x64

    int n_tile = blockIdx.x & (N_TILES - 1);   // N-fast: wave shares W in L2
    int m_tile = blockIdx.x >> 4;
    int m0 = m_tile * BM, n0 = n_tile * BN;

    // ---- aux: hc (4KB), U (8KB), bias (1KB) ----
    if (tid < 256) {
        int row = tid >> 1, half = tid & 1;
        float4 h = *reinterpret_cast<const float4*>(&g_hc[(size_t)(m0 + row) * RANK + half * 4]);
        *reinterpret_cast<float4*>(smem + SM_AUX + (row * 8 + half * 4) * 4) = h;
#pragma unroll
        for (int p = 0; p < 2; ++p) {
            float4 u = *reinterpret_cast<const float4*>(&U[(size_t)(n0 + tid) * RANK + p * 4]);
            *reinterpret_cast<float4*>(smem + SM_AUX + 4096 + (tid * 8 + p * 4) * 4) = u;
        }
        *reinterpret_cast<float*>(smem + SM_AUX + 12288 + tid * 4) = bias[n0 + tid];
    }

    float acc[2][8][4];
#pragma unroll
    for (int a = 0; a < 2; ++a)
#pragma unroll
        for (int c = 0; c < 8; ++c)
#pragma unroll
            for (int e = 0; e < 4; ++e) acc[a][c][e] = 0.f;

    const __half* xbase = &g_xh[(size_t)m0 * K_TOTAL];
    const __half* wbase = &g_wh[(size_t)n0 * K_TOTAL];

    // always commits exactly one group (possibly empty) so wait counts stay uniform
    auto LOAD = [&](int i) {
        if (i < NITER) {
            int kb = i * BK;
            uint32_t st = sb + (uint32_t)(i & (STAGES - 1)) * SM_STAGE;
            {   // A: 512 chunks, one per thread
                int row = tid >> 2, kc = tid & 3;
                cp_async16(st + swz(row, kc), xbase + (size_t)row * K_TOTAL + kb + kc * 8);
            }
#pragma unroll
            for (int p = 0; p < 2; ++p) {    // B: 1024 chunks
                int id = tid + p * 512;
                int row = id >> 2, kc = id & 3;
                cp_async16(st + 8192 + swz(row, kc), wbase + (size_t)row * K_TOTAL + kb + kc * 8);
            }
        }
        cp_commit();
    };

    // ldmatrix lane geometry (constant across iters)
    int rowA = wm * 32 + ((lane >> 3) & 1) * 8 + (lane & 7);
    int aKc  = lane >> 4;
    int sA   = (rowA >> 1) & 3;
    int rowB = wn * 64 + ((lane >> 4) & 1) * 8 + (lane & 7);
    int bKc  = (lane >> 3) & 1;
    int sB   = (rowB >> 1) & 3;

    auto COMPUTE = [&](int i) {
        uint32_t st = sb + (uint32_t)(i & (STAGES - 1)) * SM_STAGE;
#pragma unroll
        for (int ks = 0; ks < 2; ++ks) {
            uint32_t afrag[2][4], bfrag[8][2];
            uint32_t akc = (uint32_t)(((ks * 2 + aKc) ^ sA) << 4);
            uint32_t bkc = (uint32_t)(((ks * 2 + bKc) ^ sB) << 4);
#pragma unroll
            for (int tm = 0; tm < 2; ++tm)
                ldsm4(afrag[tm], st + (uint32_t)((rowA + tm * 16) * 64) + akc);
#pragma unroll
            for (int p = 0; p < 4; ++p) {
                uint32_t r[4];
                ldsm4(r, st + 8192 + (uint32_t)((rowB + p * 16) * 64) + bkc);
                bfrag[p * 2 + 0][0] = r[0]; bfrag[p * 2 + 0][1] = r[1];
                bfrag[p * 2 + 1][0] = r[2]; bfrag[p * 2 + 1][1] = r[3];
            }
#pragma unroll
            for (int tm = 0; tm < 2; ++tm)
#pragma unroll
                for (int tn = 0; tn < 8; ++tn)
                    mma_f16(acc[tm][tn], afrag[tm], bfrag[tn]);
        }
    };

    // prologue: load first 4 chunks (stages 0..3)
#pragma unroll
    for (int i = 0; i < 4; ++i) LOAD(i);

    // mainloop: one wait+barrier per 4 K-chunks.
    // At quad start, the only pending groups are chunks i..i+3 -> wait all.
    // Loads issued in this quad (i+4..i+7) write stages consumed in the
    // PREVIOUS quad; the barrier below guarantees all warps have left them.
    for (int i = 0; i < NITER; i += 4) {
        cp_wait<0>();
        __syncthreads();
        COMPUTE(i);     LOAD(i + 4);
        COMPUTE(i + 1); LOAD(i + 5);
        COMPUTE(i + 2); LOAD(i + 6);
        COMPUTE(i + 3); LOAD(i + 7);
    }

    // ---- epilogue: out = acc + bias[n] + sum_r hc[m,r]*U[n,r] ----
    const float* shc   = reinterpret_cast<const float*>(smem + SM_AUX);
    const float* sU    = reinterpret_cast<const float*>(smem + SM_AUX + 4096);
    const float* sbias = reinterpret_cast<const float*>(smem + SM_AUX + 12288);
    int r = lane >> 2, cq = lane & 3;
#pragma unroll
    for (int tm = 0; tm < 2; ++tm) {
        int mA = wm * 32 + tm * 16 + r;        // rows mA and mA+8
        float hA[8], hB[8];
#pragma unroll
        for (int q = 0; q < 8; ++q) { hA[q] = shc[mA * 8 + q]; hB[q] = shc[(mA + 8) * 8 + q]; }
#pragma unroll
        for (int tn = 0; tn < 8; ++tn) {
            int nb = wn * 64 + tn * 8 + cq * 2;
#pragma unroll
            for (int p = 0; p < 2; ++p) {
                int m = p ? (mA + 8) : mA;
                const float* h = p ? hB : hA;
                float2 o;
#pragma unroll
                for (int e = 0; e < 2; ++e) {
                    int n = nb + e;
                    float lora = 0.f;
#pragma unroll
                    for (int q = 0; q < 8; ++q) lora += h[q] * sU[n * 8 + q];
                    float v = acc[tm][tn][p * 2 + e] + sbias[n] + lora;
                    if (e == 0) o.x = v; else o.y = v;
                }
                *reinterpret_cast<float2*>(&out[(size_t)(m0 + m) * N_TOTAL + n0 + nb]) = o;
            }
        }
    }
}

extern "C" void kernel_launch(void* const* d_in, const int* in_sizes, int n_in,
                              void* d_out, int out_size) {
    const float* x     = (const float*)d_in[0];
    const float* codes = (const float*)d_in[1];
    const float* W     = (const float*)d_in[2];
    const float* bb    = (const float*)d_in[3];
    const float* V     = (const float*)d_in[4];
    const float* U     = (const float*)d_in[5];
    float* out = (float*)d_out;

    cudaFuncSetAttribute(prep_kernel, cudaFuncAttributeMaxDynamicSharedMemorySize, 131072);
    cudaFuncSetAttribute(gemm_kernel, cudaFuncAttributeMaxDynamicSharedMemorySize, SMEM_TOTAL);

    prep_kernel<<<148, 1024, 131072>>>(x, codes, V, W);
    gemm_kernel<<<M_TILES * N_TILES, THREADS, SMEM_TOTAL>>>(bb, U, out);
}

// round 11
// speedup vs baseline: 1.1427x; 1.1427x over previous
#include <cuda_runtime.h>
#include <cuda_fp16.h>
#include <cstdint>

#define M_TOTAL 16384
#define N_TOTAL 4096
#define K_TOTAL 4096
#define RANK    8

#define BM 128
#define BN 128
#define BK 32
#define NITER   (K_TOTAL / BK)     // 128
#define THREADS 256
#define STAGES  4
#define N_TILES (N_TOTAL / BN)     // 32
#define M_TILES (M_TOTAL / BM)     // 128

#define SM_STAGE 16384             // A 8KB + B 8KB (fp16)
#define SM_AUX   (STAGES * SM_STAGE)      // 65536
#define SMEM_TOTAL (SM_AUX + 4096 + 4096 + 512)   // 74240  (x2 CTAs = 148.5KB)

static __device__ float  g_hc[M_TOTAL * RANK];
static __device__ __half g_xh[(size_t)M_TOTAL * K_TOTAL];   // 128 MB
static __device__ __half g_wh[(size_t)N_TOTAL * K_TOTAL];   // 32 MB

// ---------------- helpers ----------------
__device__ __forceinline__ uint32_t smem_u32(const void* p) {
    uint32_t a;
    asm("{ .reg .u64 t; cvta.to.shared.u64 t, %1; cvt.u32.u64 %0, t; }" : "=r"(a) : "l"(p));
    return a;
}
__device__ __forceinline__ void cp_async16(uint32_t dst, const void* src) {
    asm volatile("cp.async.cg.shared.global [%0], [%1], 16;" :: "r"(dst), "l"(src) : "memory");
}
__device__ __forceinline__ void cp_commit() {
    asm volatile("cp.async.commit_group;" ::: "memory");
}
template <int N>
__device__ __forceinline__ void cp_wait() {
    asm volatile("cp.async.wait_group %0;" :: "n"(N) : "memory");
}
__device__ __forceinline__ void ldsm4(uint32_t* r, uint32_t a) {
    asm volatile("ldmatrix.sync.aligned.m8n8.x4.shared.b16 {%0,%1,%2,%3}, [%4];"
                 : "=r"(r[0]), "=r"(r[1]), "=r"(r[2]), "=r"(r[3]) : "r"(a));
}
__device__ __forceinline__ void mma_f16(float* d, const uint32_t* a, const uint32_t* b) {
    asm volatile("mma.sync.aligned.m16n8k16.row.col.f32.f16.f16.f32 "
                 "{%0,%1,%2,%3}, {%4,%5,%6,%7}, {%8,%9}, {%0,%1,%2,%3};"
                 : "+f"(d[0]), "+f"(d[1]), "+f"(d[2]), "+f"(d[3])
                 : "r"(a[0]), "r"(a[1]), "r"(a[2]), "r"(a[3]), "r"(b[0]), "r"(b[1]));
}
// row-major fp16 tile, 32 halves (64B = 4x16B chunks) per row, XOR swizzle
__device__ __forceinline__ uint32_t swz(int row, int kc) {
    return (uint32_t)(row * 64 + ((kc ^ ((row >> 1) & 3)) << 4));
}

// ---------------- fused prep: convw (all blocks) + hc/convx (blocks<128) ----
__global__ void __launch_bounds__(1024) prep_kernel(
    const float* __restrict__ x, const float* __restrict__ codes,
    const float* __restrict__ V, const float* __restrict__ W)
{
    extern __shared__ float sVT[];   // [8][4096] = 128 KB
    int tid = threadIdx.x;

    // phase 1: W -> fp16, grid-stride over all blocks
    {
        size_t total = (size_t)N_TOTAL * K_TOTAL;
        size_t stride = (size_t)gridDim.x * 1024 * 4;
        for (size_t i = ((size_t)blockIdx.x * 1024 + tid) * 4; i < total; i += stride) {
            float4 v = *reinterpret_cast<const float4*>(&W[i]);
            __half2* dst = reinterpret_cast<__half2*>(&g_wh[i]);
            dst[0] = __floats2half2_rn(v.x, v.y);
            dst[1] = __floats2half2_rn(v.z, v.w);
        }
    }
    if (blockIdx.x >= 128) return;

    // phase 2: hc[m,r] = 2*codes[m,r]*sum_d x[m,d]*V[d,r]  +  x -> fp16
    for (int idx = tid; idx < K_TOTAL * RANK; idx += 1024) {
        int d = idx >> 3, r = idx & 7;
        sVT[r * K_TOTAL + d] = V[idx];
    }
    __syncthreads();

    int wid = tid >> 5, lane = tid & 31;
    int m0 = blockIdx.x * 128 + wid * 4;

    float acc[4][8];
#pragma unroll
    for (int a = 0; a < 4; ++a)
#pragma unroll
        for (int r = 0; r < 8; ++r) acc[a][r] = 0.f;

    for (int it = 0; it < 32; ++it) {
        int d = it * 128 + lane * 4;
        float4 xr[4];
#pragma unroll
        for (int a = 0; a < 4; ++a) {
            xr[a] = *reinterpret_cast<const float4*>(&x[(size_t)(m0 + a) * K_TOTAL + d]);
            __half2* dst = reinterpret_cast<__half2*>(&g_xh[(size_t)(m0 + a) * K_TOTAL + d]);
            dst[0] = __floats2half2_rn(xr[a].x, xr[a].y);
            dst[1] = __floats2half2_rn(xr[a].z, xr[a].w);
        }
#pragma unroll
        for (int r = 0; r < 8; ++r) {
            float4 v = *reinterpret_cast<const float4*>(&sVT[r * K_TOTAL + d]);
#pragma unroll
            for (int a = 0; a < 4; ++a)
                acc[a][r] += xr[a].x * v.x + xr[a].y * v.y + xr[a].z * v.z + xr[a].w * v.w;
        }
    }
#pragma unroll
    for (int o = 16; o > 0; o >>= 1)
#pragma unroll
        for (int a = 0; a < 4; ++a)
#pragma unroll
            for (int r = 0; r < 8; ++r)
                acc[a][r] += __shfl_xor_sync(0xffffffffu, acc[a][r], o);

    if (lane == 0) {
#pragma unroll
        for (int a = 0; a < 4; ++a)
#pragma unroll
            for (int r = 0; r < 8; ++r)
                g_hc[(size_t)(m0 + a) * RANK + r] =
                    2.0f * codes[(size_t)(m0 + a) * RANK + r] * acc[a][r];
    }
}

// -------- main GEMM: fp16 mma.sync m16n8k16, cp.async 4-stage ring ---------
// (R5 geometry: CTA 128x128, 256 thr, warp 64x32, 2 CTAs/SM)
__global__ void __launch_bounds__(THREADS, 2) gemm_kernel(
    const float* __restrict__ bias, const float* __restrict__ U,
    float* __restrict__ out)
{
    extern __shared__ char smem[];
    uint32_t sb = smem_u32(smem);
    int tid = threadIdx.x, lane = tid & 31, wid = tid >> 5;
    int wm = wid & 1, wn = wid >> 1;        // warp grid 2(M) x 4(N), tile 64x32

    int n_tile = blockIdx.x & (N_TILES - 1);   // N-fast: wave shares W in L2
    int m_tile = blockIdx.x >> 5;
    int m0 = m_tile * BM, n0 = n_tile * BN;

    // ---- aux: hc tile, U tile, bias tile into smem ----
    {
        int row = tid >> 1, half = tid & 1;
        float4 h = *reinterpret_cast<const float4*>(&g_hc[(size_t)(m0 + row) * RANK + half * 4]);
        *reinterpret_cast<float4*>(smem + SM_AUX + (row * 8 + half * 4) * 4) = h;
        float4 u = *reinterpret_cast<const float4*>(&U[(size_t)(n0 + row) * RANK + half * 4]);
        *reinterpret_cast<float4*>(smem + SM_AUX + 4096 + (row * 8 + half * 4) * 4) = u;
        if (tid < BN)
            *reinterpret_cast<float*>(smem + SM_AUX + 8192 + tid * 4) = bias[n0 + tid];
    }

    float acc[4][4][4];
#pragma unroll
    for (int a = 0; a < 4; ++a)
#pragma unroll
        for (int c = 0; c < 4; ++c)
#pragma unroll
            for (int e = 0; e < 4; ++e) acc[a][c][e] = 0.f;

    // cp.async indices: this thread copies 2 A-chunks + 2 B-chunks per iter
    int idA0 = tid, idA1 = tid + 256;          // chunk ids 0..511: row=id>>2, kc=id&3
    const __half* xbase = &g_xh[(size_t)m0 * K_TOTAL];
    const __half* wbase = &g_wh[(size_t)n0 * K_TOTAL];

    auto LOAD = [&](int i) {
        int kb = i * BK;
        uint32_t st = sb + (uint32_t)(i & (STAGES - 1)) * SM_STAGE;
#pragma unroll
        for (int p = 0; p < 2; ++p) {
            int id = p ? idA1 : idA0;
            int row = id >> 2, kc = id & 3;
            cp_async16(st + swz(row, kc), xbase + (size_t)row * K_TOTAL + kb + kc * 8);
            cp_async16(st + 8192 + swz(row, kc), wbase + (size_t)row * K_TOTAL + kb + kc * 8);
        }
        cp_commit();
    };

    // ldmatrix lane geometry (constant across iters)
    int rowA = wm * 64 + ((lane >> 3) & 1) * 8 + (lane & 7);
    int aKc  = lane >> 4;
    int sA   = (rowA >> 1) & 3;
    int rowB = wn * 32 + ((lane >> 4) & 1) * 8 + (lane & 7);
    int bKc  = (lane >> 3) & 1;
    int sB   = (rowB >> 1) & 3;

    auto COMPUTE = [&](int i) {
        uint32_t st = sb + (uint32_t)(i & (STAGES - 1)) * SM_STAGE;
#pragma unroll
        for (int ks = 0; ks < 2; ++ks) {
            uint32_t afrag[4][4], bfrag[4][2];
            uint32_t akc = (uint32_t)(((ks * 2 + aKc) ^ sA) << 4);
            uint32_t bkc = (uint32_t)(((ks * 2 + bKc) ^ sB) << 4);
#pragma unroll
            for (int tm = 0; tm < 4; ++tm)
                ldsm4(afrag[tm], st + (uint32_t)((rowA + tm * 16) * 64) + akc);
#pragma unroll
            for (int p = 0; p < 2; ++p) {
                uint32_t r[4];
                ldsm4(r, st + 8192 + (uint32_t)((rowB + p * 16) * 64) + bkc);
                bfrag[p * 2 + 0][0] = r[0]; bfrag[p * 2 + 0][1] = r[1];
                bfrag[p * 2 + 1][0] = r[2]; bfrag[p * 2 + 1][1] = r[3];
            }
#pragma unroll
            for (int tm = 0; tm < 4; ++tm)
#pragma unroll
                for (int tn = 0; tn < 4; ++tn)
                    mma_f16(acc[tm][tn], afrag[tm], bfrag[tn]);
        }
    };

    LOAD(0); LOAD(1); LOAD(2);
    for (int i = 0; i < NITER - 3; ++i) {
        cp_wait<2>();
        __syncthreads();
        LOAD(i + 3);
        COMPUTE(i);
    }
    cp_wait<2>(); __syncthreads(); COMPUTE(NITER - 3);
    cp_wait<1>(); __syncthreads(); COMPUTE(NITER - 2);
    cp_wait<0>(); __syncthreads(); COMPUTE(NITER - 1);

    // ---- epilogue: out = acc + bias[n] + sum_r hc[m,r]*U[n,r] ----
    const float* shc   = reinterpret_cast<const float*>(smem + SM_AUX);
    const float* sU    = reinterpret_cast<const float*>(smem + SM_AUX + 4096);
    const float* sbias = reinterpret_cast<const float*>(smem + SM_AUX + 8192);
    int r = lane >> 2, cq = lane & 3;
#pragma unroll
    for (int tm = 0; tm < 4; ++tm) {
        int mA = wm * 64 + tm * 16 + r;        // rows mA and mA+8
        float hA[8], hB[8];
#pragma unroll
        for (int q = 0; q < 8; ++q) { hA[q] = shc[mA * 8 + q]; hB[q] = shc[(mA + 8) * 8 + q]; }
#pragma unroll
        for (int tn = 0; tn < 4; ++tn) {
            int nb = wn * 32 + tn * 8 + cq * 2;
#pragma unroll
            for (int p = 0; p < 2; ++p) {
                int m = p ? (mA + 8) : mA;
                const float* h = p ? hB : hA;
                float2 o;
#pragma unroll
                for (int e = 0; e < 2; ++e) {
                    int n = nb + e;
                    float lora = 0.f;
#pragma unroll
                    for (int q = 0; q < 8; ++q) lora += h[q] * sU[n * 8 + q];
                    float v = acc[tm][tn][p * 2 + e] + sbias[n] + lora;
                    if (e == 0) o.x = v; else o.y = v;
                }
                *reinterpret_cast<float2*>(&out[(size_t)(m0 + m) * N_TOTAL + n0 + nb]) = o;
            }
        }
    }
}

extern "C" void kernel_launch(void* const* d_in, const int* in_sizes, int n_in,
                              void* d_out, int out_size) {
    const float* x     = (const float*)d_in[0];
    const float* codes = (const float*)d_in[1];
    const float* W     = (const float*)d_in[2];
    const float* bb    = (const float*)d_in[3];
    const float* V     = (const float*)d_in[4];
    const float* U     = (const float*)d_in[5];
    float* out = (float*)d_out;

    cudaFuncSetAttribute(prep_kernel, cudaFuncAttributeMaxDynamicSharedMemorySize, 131072);
    cudaFuncSetAttribute(gemm_kernel, cudaFuncAttributeMaxDynamicSharedMemorySize, SMEM_TOTAL);

    prep_kernel<<<148, 1024, 131072>>>(x, codes, V, W);
    gemm_kernel<<<M_TILES * N_TILES, THREADS, SMEM_TOTAL>>>(bb, U, out);
}

// round 12
// speedup vs baseline: 1.2050x; 1.0546x over previous
#include <cuda_runtime.h>
#include <cuda_fp16.h>
#include <cstdint>

#define M_TOTAL 16384
#define N_TOTAL 4096
#define K_TOTAL 4096
#define RANK    8

#define BM 128
#define BN 128
#define BK 64
#define NITER   (K_TOTAL / BK)     // 64
#define THREADS 256
#define STAGES  3
#define N_TILES (N_TOTAL / BN)     // 32
#define M_TILES (M_TOTAL / BM)     // 128

#define SM_STAGE 32768             // A 16KB + B 16KB (fp16, BK=64)
#define SM_AUX   (STAGES * SM_STAGE)      // 98304
#define SMEM_TOTAL (SM_AUX + 4096 + 4096 + 512)   // 107008 (x2 CTAs = 214KB)

static __device__ float  g_hc[M_TOTAL * RANK];
static __device__ __half g_xh[(size_t)M_TOTAL * K_TOTAL];   // 128 MB
static __device__ __half g_wh[(size_t)N_TOTAL * K_TOTAL];   // 32 MB

// ---------------- helpers ----------------
__device__ __forceinline__ uint32_t smem_u32(const void* p) {
    uint32_t a;
    asm("{ .reg .u64 t; cvta.to.shared.u64 t, %1; cvt.u32.u64 %0, t; }" : "=r"(a) : "l"(p));
    return a;
}
__device__ __forceinline__ void cp_async16(uint32_t dst, const void* src) {
    asm volatile("cp.async.cg.shared.global [%0], [%1], 16;" :: "r"(dst), "l"(src) : "memory");
}
__device__ __forceinline__ void cp_commit() {
    asm volatile("cp.async.commit_group;" ::: "memory");
}
template <int N>
__device__ __forceinline__ void cp_wait() {
    asm volatile("cp.async.wait_group %0;" :: "n"(N) : "memory");
}
__device__ __forceinline__ void ldsm4(uint32_t* r, uint32_t a) {
    asm volatile("ldmatrix.sync.aligned.m8n8.x4.shared.b16 {%0,%1,%2,%3}, [%4];"
                 : "=r"(r[0]), "=r"(r[1]), "=r"(r[2]), "=r"(r[3]) : "r"(a));
}
__device__ __forceinline__ void mma_f16(float* d, const uint32_t* a, const uint32_t* b) {
    asm volatile("mma.sync.aligned.m16n8k16.row.col.f32.f16.f16.f32 "
                 "{%0,%1,%2,%3}, {%4,%5,%6,%7}, {%8,%9}, {%0,%1,%2,%3};"
                 : "+f"(d[0]), "+f"(d[1]), "+f"(d[2]), "+f"(d[3])
                 : "r"(a[0]), "r"(a[1]), "r"(a[2]), "r"(a[3]), "r"(b[0]), "r"(b[1]));
}
// BK=64 row = 128B = 8 chunks of 16B; XOR swizzle by row&7 keeps cp.async
// stores and ldmatrix reads conflict-free.
__device__ __forceinline__ uint32_t swz(int row, int kc) {
    return (uint32_t)(row * 128 + ((kc ^ (row & 7)) << 4));
}

// ---------------- fused prep: convw (all blocks) + hc/convx (blocks<128) ----
__global__ void __launch_bounds__(1024) prep_kernel(
    const float* __restrict__ x, const float* __restrict__ codes,
    const float* __restrict__ V, const float* __restrict__ W)
{
    extern __shared__ float sVT[];   // [8][4096] = 128 KB
    int tid = threadIdx.x;

    // phase 1: W -> fp16, grid-stride over all blocks
    {
        size_t total = (size_t)N_TOTAL * K_TOTAL;
        size_t stride = (size_t)gridDim.x * 1024 * 4;
        for (size_t i = ((size_t)blockIdx.x * 1024 + tid) * 4; i < total; i += stride) {
            float4 v = *reinterpret_cast<const float4*>(&W[i]);
            __half2* dst = reinterpret_cast<__half2*>(&g_wh[i]);
            dst[0] = __floats2half2_rn(v.x, v.y);
            dst[1] = __floats2half2_rn(v.z, v.w);
        }
    }
    if (blockIdx.x >= 128) return;

    // phase 2: hc[m,r] = 2*codes[m,r]*sum_d x[m,d]*V[d,r]  +  x -> fp16
    for (int idx = tid; idx < K_TOTAL * RANK; idx += 1024) {
        int d = idx >> 3, r = idx & 7;
        sVT[r * K_TOTAL + d] = V[idx];
    }
    __syncthreads();

    int wid = tid >> 5, lane = tid & 31;
    int m0 = blockIdx.x * 128 + wid * 4;

    float acc[4][8];
#pragma unroll
    for (int a = 0; a < 4; ++a)
#pragma unroll
        for (int r = 0; r < 8; ++r) acc[a][r] = 0.f;

    for (int it = 0; it < 32; ++it) {
        int d = it * 128 + lane * 4;
        float4 xr[4];
#pragma unroll
        for (int a = 0; a < 4; ++a) {
            xr[a] = *reinterpret_cast<const float4*>(&x[(size_t)(m0 + a) * K_TOTAL + d]);
            __half2* dst = reinterpret_cast<__half2*>(&g_xh[(size_t)(m0 + a) * K_TOTAL + d]);
            dst[0] = __floats2half2_rn(xr[a].x, xr[a].y);
            dst[1] = __floats2half2_rn(xr[a].z, xr[a].w);
        }
#pragma unroll
        for (int r = 0; r < 8; ++r) {
            float4 v = *reinterpret_cast<const float4*>(&sVT[r * K_TOTAL + d]);
#pragma unroll
            for (int a = 0; a < 4; ++a)
                acc[a][r] += xr[a].x * v.x + xr[a].y * v.y + xr[a].z * v.z + xr[a].w * v.w;
        }
    }
#pragma unroll
    for (int o = 16; o > 0; o >>= 1)
#pragma unroll
        for (int a = 0; a < 4; ++a)
#pragma unroll
            for (int r = 0; r < 8; ++r)
                acc[a][r] += __shfl_xor_sync(0xffffffffu, acc[a][r], o);

    if (lane == 0) {
#pragma unroll
        for (int a = 0; a < 4; ++a)
#pragma unroll
            for (int r = 0; r < 8; ++r)
                g_hc[(size_t)(m0 + a) * RANK + r] =
                    2.0f * codes[(size_t)(m0 + a) * RANK + r] * acc[a][r];
    }
}

// -------- main GEMM: fp16 m16n8k16, CTA 128x128, warp 64x32, 2 CTAs/SM,
//          BK=64, 3-stage cp.async ring, ONE barrier per 64 K-cols --------
__global__ void __launch_bounds__(THREADS, 2) gemm_kernel(
    const float* __restrict__ bias, const float* __restrict__ U,
    float* __restrict__ out)
{
    extern __shared__ char smem[];
    uint32_t sb = smem_u32(smem);
    int tid = threadIdx.x, lane = tid & 31, wid = tid >> 5;
    int wm = wid & 1, wn = wid >> 1;        // warp grid 2(M) x 4(N), tile 64x32

    int n_tile = blockIdx.x & (N_TILES - 1);   // N-fast: wave shares W in L2
    int m_tile = blockIdx.x >> 5;
    int m0 = m_tile * BM, n0 = n_tile * BN;

    // ---- aux: hc tile, U tile, bias tile into smem ----
    {
        int row = tid >> 1, half = tid & 1;
        float4 h = *reinterpret_cast<const float4*>(&g_hc[(size_t)(m0 + row) * RANK + half * 4]);
        *reinterpret_cast<float4*>(smem + SM_AUX + (row * 8 + half * 4) * 4) = h;
        float4 u = *reinterpret_cast<const float4*>(&U[(size_t)(n0 + row) * RANK + half * 4]);
        *reinterpret_cast<float4*>(smem + SM_AUX + 4096 + (row * 8 + half * 4) * 4) = u;
        if (tid < BN)
            *reinterpret_cast<float*>(smem + SM_AUX + 8192 + tid * 4) = bias[n0 + tid];
    }

    float acc[4][4][4];
#pragma unroll
    for (int a = 0; a < 4; ++a)
#pragma unroll
        for (int c = 0; c < 4; ++c)
#pragma unroll
            for (int e = 0; e < 4; ++e) acc[a][c][e] = 0.f;

    const __half* xbase = &g_xh[(size_t)m0 * K_TOTAL];
    const __half* wbase = &g_wh[(size_t)n0 * K_TOTAL];

    // always commits exactly one group so wait counts stay uniform
    auto LOAD = [&](int i) {
        if (i < NITER) {
            int kb = i * BK;
            uint32_t st = sb + (uint32_t)(i % STAGES) * SM_STAGE;
#pragma unroll
            for (int p = 0; p < 4; ++p) {    // A: 1024 chunks (128 rows x 8)
                int id = tid + p * 256;
                int row = id >> 3, kc = id & 7;
                cp_async16(st + swz(row, kc), xbase + (size_t)row * K_TOTAL + kb + kc * 8);
            }
#pragma unroll
            for (int p = 0; p < 4; ++p) {    // B: 1024 chunks
                int id = tid + p * 256;
                int row = id >> 3, kc = id & 7;
                cp_async16(st + 16384 + swz(row, kc), wbase + (size_t)row * K_TOTAL + kb + kc * 8);
            }
        }
        cp_commit();
    };

    // ldmatrix lane geometry (constant across iters)
    int rowA = wm * 64 + (lane & 15);
    int aKc  = lane >> 4;                  // 0/1: which 16B half of the k16 slice
    int sA   = rowA & 7;
    int rowB = wn * 32 + ((lane >> 4) & 1) * 8 + (lane & 7);
    int bKc  = (lane >> 3) & 1;
    int sB   = rowB & 7;

    auto COMPUTE = [&](int i) {
        uint32_t st = sb + (uint32_t)(i % STAGES) * SM_STAGE;
#pragma unroll
        for (int ks = 0; ks < 4; ++ks) {
            uint32_t afrag[4][4], bfrag[4][2];
            uint32_t akc = (uint32_t)(((ks * 2 + aKc) ^ sA) << 4);
            uint32_t bkc = (uint32_t)(((ks * 2 + bKc) ^ sB) << 4);
#pragma unroll
            for (int tm = 0; tm < 4; ++tm)
                ldsm4(afrag[tm], st + (uint32_t)((rowA + tm * 16) * 128) + akc);
#pragma unroll
            for (int p = 0; p < 2; ++p) {
                uint32_t r[4];
                ldsm4(r, st + 16384 + (uint32_t)((rowB + p * 16) * 128) + bkc);
                bfrag[p * 2 + 0][0] = r[0]; bfrag[p * 2 + 0][1] = r[1];
                bfrag[p * 2 + 1][0] = r[2]; bfrag[p * 2 + 1][1] = r[3];
            }
#pragma unroll
            for (int tm = 0; tm < 4; ++tm)
#pragma unroll
                for (int tn = 0; tn < 4; ++tn)
                    mma_f16(acc[tm][tn], afrag[tm], bfrag[tn]);
        }
    };

    LOAD(0); LOAD(1);
    for (int i = 0; i < NITER; ++i) {
        cp_wait<1>();                 // stage i complete, i+1 in flight
        __syncthreads();              // everyone done with stage (i-1)%3 (= (i+2)%3)
        LOAD(i + 2);
        COMPUTE(i);
    }

    // ---- epilogue: out = acc + bias[n] + sum_r hc[m,r]*U[n,r] ----
    const float* shc   = reinterpret_cast<const float*>(smem + SM_AUX);
    const float* sU    = reinterpret_cast<const float*>(smem + SM_AUX + 4096);
    const float* sbias = reinterpret_cast<const float*>(smem + SM_AUX + 8192);
    int r = lane >> 2, cq = lane & 3;
#pragma unroll
    for (int tm = 0; tm < 4; ++tm) {
        int mA = wm * 64 + tm * 16 + r;        // rows mA and mA+8
        float hA[8], hB[8];
#pragma unroll
        for (int q = 0; q < 8; ++q) { hA[q] = shc[mA * 8 + q]; hB[q] = shc[(mA + 8) * 8 + q]; }
#pragma unroll
        for (int tn = 0; tn < 4; ++tn) {
            int nb = wn * 32 + tn * 8 + cq * 2;
#pragma unroll
            for (int p = 0; p < 2; ++p) {
                int m = p ? (mA + 8) : mA;
                const float* h = p ? hB : hA;
                float2 o;
#pragma unroll
                for (int e = 0; e < 2; ++e) {
                    int n = nb + e;
                    float lora = 0.f;
#pragma unroll
                    for (int q = 0; q < 8; ++q) lora += h[q] * sU[n * 8 + q];
                    float v = acc[tm][tn][p * 2 + e] + sbias[n] + lora;
                    if (e == 0) o.x = v; else o.y = v;
                }
                *reinterpret_cast<float2*>(&out[(size_t)(m0 + m) * N_TOTAL + n0 + nb]) = o;
            }
        }
    }
}

extern "C" void kernel_launch(void* const* d_in, const int* in_sizes, int n_in,
                              void* d_out, int out_size) {
    const float* x     = (const float*)d_in[0];
    const float* codes = (const float*)d_in[1];
    const float* W     = (const float*)d_in[2];
    const float* bb    = (const float*)d_in[3];
    const float* V     = (const float*)d_in[4];
    const float* U     = (const float*)d_in[5];
    float* out = (float*)d_out;

    cudaFuncSetAttribute(prep_kernel, cudaFuncAttributeMaxDynamicSharedMemorySize, 131072);
    cudaFuncSetAttribute(gemm_kernel, cudaFuncAttributeMaxDynamicSharedMemorySize, SMEM_TOTAL);

    prep_kernel<<<148, 1024, 131072>>>(x, codes, V, W);
    gemm_kernel<<<M_TILES * N_TILES, THREADS, SMEM_TOTAL>>>(bb, U, out);
}